// round 1
// baseline (speedup 1.0000x reference)
#include <cuda_runtime.h>
#include <cuda_bf16.h>
#include <math.h>

// ---------------------------------------------------------------------------
// DSQGAttention: qkv = x @ w_qkv ; gather-attention over 44 fixed offsets ;
// out = (attn * gain) @ w_out
// Shapes: B=1, T=2048, C=1024, H=16, HD=64, J=44
// ---------------------------------------------------------------------------

#define T_DIM 2048
#define C_DIM 1024
#define H_DIM 16
#define HD_DIM 64
#define J_DIM 44
#define QKV_N 3072

// Scratch (allocation-free rule: __device__ globals)
__device__ float g_qkv[T_DIM * QKV_N];     // 25.2 MB
__device__ float g_attn[T_DIM * C_DIM];    // 8 MB

__constant__ int c_deltas[J_DIM] = {
    0,1,2,3,4,5,6,7,8,9,10,11,12,13,14,15,16,17,18,19,
    20,21,22,23,24,25,26,27,28,29,30,31,32,33,34,35,36,37,38,39,
    40,128,384,1536
};

// ---------------------------------------------------------------------------
// Tiled fp32 SGEMM: C[M,N] = A[M,K] @ B[K,N], all row-major.
// BM=BN=128, BK=8, 256 threads, 8x8 per thread.
// Requires M%128==0, N%128==0, K%8==0 (true for all our shapes).
// ---------------------------------------------------------------------------
__global__ __launch_bounds__(256, 2)
void sgemm_kernel(const float* __restrict__ A, const float* __restrict__ B,
                  float* __restrict__ C, int M, int N, int K)
{
    const int BM = 128, BN = 128, BK = 8;
    __shared__ float As[BK][BM];
    __shared__ float Bs[BK][BN];

    int tid = threadIdx.x;
    int bm = blockIdx.y * BM;
    int bn = blockIdx.x * BN;

    // A tile loader: 128 rows x 8 cols = 1024 floats; one float4 per thread
    int arow = tid >> 1;           // 0..127
    int acol = (tid & 1) * 4;      // 0 or 4
    // B tile loader: 8 rows x 128 cols; one float4 per thread
    int brow = tid >> 5;           // 0..7
    int bcol = (tid & 31) * 4;     // 0..124

    int tx = tid & 15;             // 0..15 -> col group
    int ty = tid >> 4;             // 0..15 -> row group

    float acc[8][8];
#pragma unroll
    for (int i = 0; i < 8; i++)
#pragma unroll
        for (int j = 0; j < 8; j++) acc[i][j] = 0.0f;

    for (int k0 = 0; k0 < K; k0 += BK) {
        float4 a4 = *(const float4*)&A[(size_t)(bm + arow) * K + k0 + acol];
        As[acol + 0][arow] = a4.x;
        As[acol + 1][arow] = a4.y;
        As[acol + 2][arow] = a4.z;
        As[acol + 3][arow] = a4.w;
        float4 b4 = *(const float4*)&B[(size_t)(k0 + brow) * N + bn + bcol];
        *(float4*)&Bs[brow][bcol] = b4;
        __syncthreads();

#pragma unroll
        for (int k = 0; k < BK; k++) {
            float ar[8], br[8];
            *(float4*)&ar[0] = *(const float4*)&As[k][ty * 8 + 0];
            *(float4*)&ar[4] = *(const float4*)&As[k][ty * 8 + 4];
            *(float4*)&br[0] = *(const float4*)&Bs[k][tx * 8 + 0];
            *(float4*)&br[4] = *(const float4*)&Bs[k][tx * 8 + 4];
#pragma unroll
            for (int i = 0; i < 8; i++)
#pragma unroll
                for (int j = 0; j < 8; j++)
                    acc[i][j] = fmaf(ar[i], br[j], acc[i][j]);
        }
        __syncthreads();
    }

#pragma unroll
    for (int i = 0; i < 8; i++) {
        int row = bm + ty * 8 + i;
        float* cp = &C[(size_t)row * N + bn + tx * 8];
        *(float4*)&cp[0] = make_float4(acc[i][0], acc[i][1], acc[i][2], acc[i][3]);
        *(float4*)&cp[4] = make_float4(acc[i][4], acc[i][5], acc[i][6], acc[i][7]);
    }
}

// ---------------------------------------------------------------------------
// Gather attention with online softmax.
// One warp per (t, h). Block = 256 threads = 8 warps = 8 consecutive t, same h.
// Each lane owns 2 head-dims (float2).
// ---------------------------------------------------------------------------
__global__ __launch_bounds__(256)
void attn_kernel(const float* __restrict__ pos_bias,    // [J, H]
                 const float* __restrict__ scale_embed, // [J, HD]
                 const float* __restrict__ if_gain)     // [H]
{
    __shared__ float s_se[J_DIM * HD_DIM];  // 1 + scale_embed
    __shared__ float s_pb[J_DIM];

    int tid  = threadIdx.x;
    int w    = blockIdx.x * 8 + (tid >> 5);
    int lane = tid & 31;
    int t    = w & (T_DIM - 1);
    int h    = w >> 11;   // all 8 warps in a block share h (2048 % 8 == 0)

    for (int i = tid; i < J_DIM * HD_DIM; i += 256)
        s_se[i] = 1.0f + scale_embed[i];
    if (tid < J_DIM)
        s_pb[tid] = pos_bias[tid * H_DIM + h];
    __syncthreads();

    const float* base = g_qkv + (size_t)t * QKV_N + h * HD_DIM;
    float2 q = *(const float2*)(base + 2 * lane);

    const float scale = 0.125f;  // 1/sqrt(64)
    float m = -1e30f, l = 0.0f;
    float accx = 0.0f, accy = 0.0f;

#pragma unroll 4
    for (int j = 0; j < J_DIM; j++) {
        int idx  = t - c_deltas[j];
        int idxc = idx < 0 ? 0 : idx;
        const float* kp = g_qkv + (size_t)idxc * QKV_N + C_DIM + h * HD_DIM + 2 * lane;
        float2 kk = *(const float2*)kp;
        float2 vv = *(const float2*)(kp + C_DIM);
        float2 se = *(const float2*)&s_se[j * HD_DIM + 2 * lane];

        float p = q.x * kk.x * se.x + q.y * kk.y * se.y;
        p += __shfl_xor_sync(0xffffffffu, p, 16);
        p += __shfl_xor_sync(0xffffffffu, p, 8);
        p += __shfl_xor_sync(0xffffffffu, p, 4);
        p += __shfl_xor_sync(0xffffffffu, p, 2);
        p += __shfl_xor_sync(0xffffffffu, p, 1);

        float s = (idx >= 0) ? fmaf(p, scale, s_pb[j]) : -1e30f;
        float mn = fmaxf(m, s);
        float corr = __expf(m - mn);
        float e = __expf(s - mn);
        l = l * corr + e;
        accx = accx * corr + e * vv.x;
        accy = accy * corr + e * vv.y;
        m = mn;
    }

    float g = if_gain[h] / l;
    float2 o = make_float2(accx * g, accy * g);
    *(float2*)&g_attn[(size_t)t * C_DIM + h * HD_DIM + 2 * lane] = o;
}

// ---------------------------------------------------------------------------
// Launch
// ---------------------------------------------------------------------------
extern "C" void kernel_launch(void* const* d_in, const int* in_sizes, int n_in,
                              void* d_out, int out_size)
{
    const float* x           = (const float*)d_in[0];  // [T, C]
    const float* w_qkv       = (const float*)d_in[1];  // [C, 3C]
    const float* w_out       = (const float*)d_in[2];  // [C, C]
    const float* pos_bias    = (const float*)d_in[3];  // [J, H]
    const float* scale_embed = (const float*)d_in[4];  // [J, HD]
    const float* if_gain     = (const float*)d_in[5];  // [H]
    float* out = (float*)d_out;

    float* qkv_ptr = nullptr;
    float* attn_ptr = nullptr;
    cudaGetSymbolAddress((void**)&qkv_ptr, g_qkv);
    cudaGetSymbolAddress((void**)&attn_ptr, g_attn);

    // GEMM1: qkv = x @ w_qkv   [2048,1024]@[1024,3072]
    {
        dim3 grid(QKV_N / 128, T_DIM / 128);
        sgemm_kernel<<<grid, 256>>>(x, w_qkv, qkv_ptr, T_DIM, QKV_N, C_DIM);
    }

    // Attention: 1 warp per (t,h)
    {
        int nwarps = T_DIM * H_DIM;
        attn_kernel<<<nwarps / 8, 256>>>(pos_bias, scale_embed, if_gain);
    }

    // GEMM2: out = attn @ w_out   [2048,1024]@[1024,1024]
    {
        dim3 grid(C_DIM / 128, T_DIM / 128);
        sgemm_kernel<<<grid, 256>>>(attn_ptr, w_out, out, T_DIM, C_DIM, C_DIM);
    }
}

// round 2
// speedup vs baseline: 2.2419x; 2.2419x over previous
#include <cuda_runtime.h>
#include <cuda_bf16.h>
#include <math.h>

// ---------------------------------------------------------------------------
// DSQGAttention: qkv = x @ w_qkv ; gather-attention over 44 fixed offsets ;
// out = (attn * gain) @ w_out
// Shapes: B=1, T=2048, C=1024, H=16, HD=64, J=44
// ---------------------------------------------------------------------------

#define T_DIM 2048
#define C_DIM 1024
#define H_DIM 16
#define HD_DIM 64
#define J_DIM 44
#define QKV_N 3072

__device__ float g_qkv[T_DIM * QKV_N];     // 25.2 MB scratch
__device__ float g_attn[T_DIM * C_DIM];    // 8 MB scratch

__constant__ int c_deltas[J_DIM] = {
    0,1,2,3,4,5,6,7,8,9,10,11,12,13,14,15,16,17,18,19,
    20,21,22,23,24,25,26,27,28,29,30,31,32,33,34,35,36,37,38,39,
    40,128,384,1536
};

__device__ __forceinline__ unsigned f2tf32(float f) {
    unsigned u;
    asm("cvt.rna.tf32.f32 %0, %1;" : "=r"(u) : "f"(f));
    return u;
}

// ---------------------------------------------------------------------------
// TF32 tensor-core GEMM: C[M,N] = A[M,K] @ B[K,N], row-major fp32 in/out.
// Block 128x128x16, 256 threads (8 warps: 2m x 4n), warp tile 64x32.
// mma.sync.m16n8k8.tf32. Requires M%128==0, N%128==0, K%16==0.
// Smem padded to 136 words -> conflict-free fragment LDS.
// Register prefetch (1 BK ahead) hides global latency.
// ---------------------------------------------------------------------------
__global__ __launch_bounds__(256)
void tf32_gemm(const float* __restrict__ A, const float* __restrict__ B,
               float* __restrict__ C, int M, int N, int K)
{
    __shared__ unsigned As[16][136];   // [k][m], tf32 bits
    __shared__ unsigned Bs[16][136];   // [k][n], tf32 bits

    const int tid = threadIdx.x;
    const int bm = blockIdx.y * 128;
    const int bn = blockIdx.x * 128;
    const int w    = tid >> 5;
    const int lane = tid & 31;
    const int wm = (w & 1) * 64;
    const int wn = (w >> 1) * 32;
    const int g   = lane >> 2;
    const int tig = lane & 3;

    // A loader: thread covers (rows tid>>2 and +64, k-cols (tid&3)*4 .. +3)
    const int arow = tid >> 2;         // 0..63
    const int acol = (tid & 3) * 4;    // 0,4,8,12
    // B loader: thread covers (k-row tid>>4, cols (tid&15)*4 and +64)
    const int brow = tid >> 4;         // 0..15
    const int bcol = (tid & 15) * 4;   // 0..60

    const float* Aptr = A + (size_t)(bm + arow) * K + acol;
    const float* Bptr = B + (size_t)brow * N + bn + bcol;

    float4 pa0, pa1, pb0, pb1;
    pa0 = *(const float4*)(Aptr);
    pa1 = *(const float4*)(Aptr + (size_t)64 * K);
    pb0 = *(const float4*)(Bptr);
    pb1 = *(const float4*)(Bptr + 64);

    float acc[4][4][4];
#pragma unroll
    for (int mt = 0; mt < 4; mt++)
#pragma unroll
        for (int nt = 0; nt < 4; nt++)
#pragma unroll
            for (int r = 0; r < 4; r++) acc[mt][nt][r] = 0.0f;

    for (int k0 = 0; k0 < K; k0 += 16) {
        // store prefetched tile (converted to tf32)
        As[acol + 0][arow]      = f2tf32(pa0.x);
        As[acol + 1][arow]      = f2tf32(pa0.y);
        As[acol + 2][arow]      = f2tf32(pa0.z);
        As[acol + 3][arow]      = f2tf32(pa0.w);
        As[acol + 0][arow + 64] = f2tf32(pa1.x);
        As[acol + 1][arow + 64] = f2tf32(pa1.y);
        As[acol + 2][arow + 64] = f2tf32(pa1.z);
        As[acol + 3][arow + 64] = f2tf32(pa1.w);
        Bs[brow][bcol + 0]      = f2tf32(pb0.x);
        Bs[brow][bcol + 1]      = f2tf32(pb0.y);
        Bs[brow][bcol + 2]      = f2tf32(pb0.z);
        Bs[brow][bcol + 3]      = f2tf32(pb0.w);
        Bs[brow][bcol + 64]     = f2tf32(pb1.x);
        Bs[brow][bcol + 65]     = f2tf32(pb1.y);
        Bs[brow][bcol + 66]     = f2tf32(pb1.z);
        Bs[brow][bcol + 67]     = f2tf32(pb1.w);
        __syncthreads();

        if (k0 + 16 < K) {
            pa0 = *(const float4*)(Aptr + k0 + 16);
            pa1 = *(const float4*)(Aptr + (size_t)64 * K + k0 + 16);
            pb0 = *(const float4*)(Bptr + (size_t)(k0 + 16) * N);
            pb1 = *(const float4*)(Bptr + (size_t)(k0 + 16) * N + 64);
        }

#pragma unroll
        for (int kk = 0; kk < 16; kk += 8) {
            unsigned af[4][4], bf[4][2];
#pragma unroll
            for (int mt = 0; mt < 4; mt++) {
                int m0 = wm + mt * 16;
                af[mt][0] = As[kk + tig][m0 + g];
                af[mt][1] = As[kk + tig][m0 + g + 8];
                af[mt][2] = As[kk + tig + 4][m0 + g];
                af[mt][3] = As[kk + tig + 4][m0 + g + 8];
            }
#pragma unroll
            for (int nt = 0; nt < 4; nt++) {
                int n0 = wn + nt * 8;
                bf[nt][0] = Bs[kk + tig][n0 + g];
                bf[nt][1] = Bs[kk + tig + 4][n0 + g];
            }
#pragma unroll
            for (int mt = 0; mt < 4; mt++)
#pragma unroll
                for (int nt = 0; nt < 4; nt++) {
                    asm volatile(
                        "mma.sync.aligned.m16n8k8.row.col.f32.tf32.tf32.f32 "
                        "{%0,%1,%2,%3}, {%4,%5,%6,%7}, {%8,%9}, {%0,%1,%2,%3};"
                        : "+f"(acc[mt][nt][0]), "+f"(acc[mt][nt][1]),
                          "+f"(acc[mt][nt][2]), "+f"(acc[mt][nt][3])
                        : "r"(af[mt][0]), "r"(af[mt][1]),
                          "r"(af[mt][2]), "r"(af[mt][3]),
                          "r"(bf[nt][0]), "r"(bf[nt][1]));
                }
        }
        __syncthreads();
    }

    // epilogue: c0,c1 at (g, tig*2), c2,c3 at (g+8, tig*2)
#pragma unroll
    for (int mt = 0; mt < 4; mt++) {
#pragma unroll
        for (int nt = 0; nt < 4; nt++) {
            int row = bm + wm + mt * 16 + g;
            int col = bn + wn + nt * 8 + tig * 2;
            *(float2*)&C[(size_t)row * N + col] =
                make_float2(acc[mt][nt][0], acc[mt][nt][1]);
            *(float2*)&C[(size_t)(row + 8) * N + col] =
                make_float2(acc[mt][nt][2], acc[mt][nt][3]);
        }
    }
}

// ---------------------------------------------------------------------------
// Gather attention with online softmax (unchanged from round 1).
// One warp per (t, h). Block = 256 threads = 8 warps.
// ---------------------------------------------------------------------------
__global__ __launch_bounds__(256)
void attn_kernel(const float* __restrict__ pos_bias,    // [J, H]
                 const float* __restrict__ scale_embed, // [J, HD]
                 const float* __restrict__ if_gain)     // [H]
{
    __shared__ float s_se[J_DIM * HD_DIM];
    __shared__ float s_pb[J_DIM];

    int tid  = threadIdx.x;
    int w    = blockIdx.x * 8 + (tid >> 5);
    int lane = tid & 31;
    int t    = w & (T_DIM - 1);
    int h    = w >> 11;

    for (int i = tid; i < J_DIM * HD_DIM; i += 256)
        s_se[i] = 1.0f + scale_embed[i];
    if (tid < J_DIM)
        s_pb[tid] = pos_bias[tid * H_DIM + h];
    __syncthreads();

    const float* base = g_qkv + (size_t)t * QKV_N + h * HD_DIM;
    float2 q = *(const float2*)(base + 2 * lane);

    const float scale = 0.125f;
    float m = -1e30f, l = 0.0f;
    float accx = 0.0f, accy = 0.0f;

#pragma unroll 4
    for (int j = 0; j < J_DIM; j++) {
        int idx  = t - c_deltas[j];
        int idxc = idx < 0 ? 0 : idx;
        const float* kp = g_qkv + (size_t)idxc * QKV_N + C_DIM + h * HD_DIM + 2 * lane;
        float2 kk = *(const float2*)kp;
        float2 vv = *(const float2*)(kp + C_DIM);
        float2 se = *(const float2*)&s_se[j * HD_DIM + 2 * lane];

        float p = q.x * kk.x * se.x + q.y * kk.y * se.y;
        p += __shfl_xor_sync(0xffffffffu, p, 16);
        p += __shfl_xor_sync(0xffffffffu, p, 8);
        p += __shfl_xor_sync(0xffffffffu, p, 4);
        p += __shfl_xor_sync(0xffffffffu, p, 2);
        p += __shfl_xor_sync(0xffffffffu, p, 1);

        float s = (idx >= 0) ? fmaf(p, scale, s_pb[j]) : -1e30f;
        float mn = fmaxf(m, s);
        float corr = __expf(m - mn);
        float e = __expf(s - mn);
        l = l * corr + e;
        accx = accx * corr + e * vv.x;
        accy = accy * corr + e * vv.y;
        m = mn;
    }

    float gn = if_gain[h] / l;
    *(float2*)&g_attn[(size_t)t * C_DIM + h * HD_DIM + 2 * lane] =
        make_float2(accx * gn, accy * gn);
}

// ---------------------------------------------------------------------------
// Launch
// ---------------------------------------------------------------------------
extern "C" void kernel_launch(void* const* d_in, const int* in_sizes, int n_in,
                              void* d_out, int out_size)
{
    const float* x           = (const float*)d_in[0];
    const float* w_qkv       = (const float*)d_in[1];
    const float* w_out       = (const float*)d_in[2];
    const float* pos_bias    = (const float*)d_in[3];
    const float* scale_embed = (const float*)d_in[4];
    const float* if_gain     = (const float*)d_in[5];
    float* out = (float*)d_out;

    float* qkv_ptr = nullptr;
    float* attn_ptr = nullptr;
    cudaGetSymbolAddress((void**)&qkv_ptr, g_qkv);
    cudaGetSymbolAddress((void**)&attn_ptr, g_attn);

    // GEMM1: qkv = x @ w_qkv   [2048,1024]@[1024,3072]
    {
        dim3 grid(QKV_N / 128, T_DIM / 128);
        tf32_gemm<<<grid, 256>>>(x, w_qkv, qkv_ptr, T_DIM, QKV_N, C_DIM);
    }

    // Attention
    {
        int nwarps = T_DIM * H_DIM;
        attn_kernel<<<nwarps / 8, 256>>>(pos_bias, scale_embed, if_gain);
    }

    // GEMM2: out = attn @ w_out   [2048,1024]@[1024,1024]
    {
        dim3 grid(C_DIM / 128, T_DIM / 128);
        tf32_gemm<<<grid, 256>>>(attn_ptr, w_out, out, T_DIM, C_DIM, C_DIM);
    }
}

// round 3
// speedup vs baseline: 2.4068x; 1.0736x over previous
#include <cuda_runtime.h>
#include <cuda_bf16.h>
#include <math.h>

// ---------------------------------------------------------------------------
// DSQGAttention: qkv = x @ w_qkv ; gather-attention over 44 fixed offsets ;
// out = (attn * gain) @ w_out
// Shapes: B=1, T=2048, C=1024, H=16, HD=64, J=44
// ---------------------------------------------------------------------------

#define T_DIM 2048
#define C_DIM 1024
#define H_DIM 16
#define HD_DIM 64
#define J_DIM 44
#define QKV_N 3072

__device__ float g_qkv[T_DIM * QKV_N];     // 25.2 MB scratch
__device__ float g_attn[T_DIM * C_DIM];    // 8 MB scratch

__constant__ int c_deltas[J_DIM] = {
    0,1,2,3,4,5,6,7,8,9,10,11,12,13,14,15,16,17,18,19,
    20,21,22,23,24,25,26,27,28,29,30,31,32,33,34,35,36,37,38,39,
    40,128,384,1536
};

__device__ __forceinline__ unsigned f2tf32(float f) {
    unsigned u;
    asm("cvt.rna.tf32.f32 %0, %1;" : "=r"(u) : "f"(f));
    return u;
}

// ---------------------------------------------------------------------------
// TF32 tensor-core GEMM, double-buffered smem.
// C[M,N] = A[M,K] @ B[K,N], row-major fp32 in/out.
// Block 128x128x16, 256 threads (8 warps: 2m x 4n), warp tile 64x32.
// One __syncthreads per BK iteration; global prefetch one BK ahead.
// ---------------------------------------------------------------------------
__global__ __launch_bounds__(256)
void tf32_gemm(const float* __restrict__ A, const float* __restrict__ B,
               float* __restrict__ C, int M, int N, int K)
{
    __shared__ unsigned As[2][16][136];
    __shared__ unsigned Bs[2][16][136];

    const int tid = threadIdx.x;
    const int bm = blockIdx.y * 128;
    const int bn = blockIdx.x * 128;
    const int w    = tid >> 5;
    const int lane = tid & 31;
    const int wm = (w & 1) * 64;
    const int wn = (w >> 1) * 32;
    const int g   = lane >> 2;
    const int tig = lane & 3;

    const int arow = tid >> 2;         // 0..63
    const int acol = (tid & 3) * 4;    // 0,4,8,12
    const int brow = tid >> 4;         // 0..15
    const int bcol = (tid & 15) * 4;   // 0..60

    const float* Aptr  = A + (size_t)(bm + arow) * K + acol;
    const float* Aptr2 = Aptr + (size_t)64 * K;
    const float* Bptr  = B + (size_t)brow * N + bn + bcol;

    float acc[4][4][4];
#pragma unroll
    for (int mt = 0; mt < 4; mt++)
#pragma unroll
        for (int nt = 0; nt < 4; nt++)
#pragma unroll
            for (int r = 0; r < 4; r++) acc[mt][nt][r] = 0.0f;

    float4 pa0 = *(const float4*)(Aptr);
    float4 pa1 = *(const float4*)(Aptr2);
    float4 pb0 = *(const float4*)(Bptr);
    float4 pb1 = *(const float4*)(Bptr + 64);

#define STORE_TILE(buf)                                   \
    do {                                                  \
        As[buf][acol + 0][arow]      = f2tf32(pa0.x);     \
        As[buf][acol + 1][arow]      = f2tf32(pa0.y);     \
        As[buf][acol + 2][arow]      = f2tf32(pa0.z);     \
        As[buf][acol + 3][arow]      = f2tf32(pa0.w);     \
        As[buf][acol + 0][arow + 64] = f2tf32(pa1.x);     \
        As[buf][acol + 1][arow + 64] = f2tf32(pa1.y);     \
        As[buf][acol + 2][arow + 64] = f2tf32(pa1.z);     \
        As[buf][acol + 3][arow + 64] = f2tf32(pa1.w);     \
        Bs[buf][brow][bcol + 0]      = f2tf32(pb0.x);     \
        Bs[buf][brow][bcol + 1]      = f2tf32(pb0.y);     \
        Bs[buf][brow][bcol + 2]      = f2tf32(pb0.z);     \
        Bs[buf][brow][bcol + 3]      = f2tf32(pb0.w);     \
        Bs[buf][brow][bcol + 64]     = f2tf32(pb1.x);     \
        Bs[buf][brow][bcol + 65]     = f2tf32(pb1.y);     \
        Bs[buf][brow][bcol + 66]     = f2tf32(pb1.z);     \
        Bs[buf][brow][bcol + 67]     = f2tf32(pb1.w);     \
    } while (0)

#define COMPUTE_TILE(buf)                                                      \
    do {                                                                       \
        _Pragma("unroll")                                                      \
        for (int kk = 0; kk < 16; kk += 8) {                                   \
            unsigned af[4][4], bf[4][2];                                       \
            _Pragma("unroll")                                                  \
            for (int mt = 0; mt < 4; mt++) {                                   \
                int m0 = wm + mt * 16;                                         \
                af[mt][0] = As[buf][kk + tig][m0 + g];                         \
                af[mt][1] = As[buf][kk + tig][m0 + g + 8];                     \
                af[mt][2] = As[buf][kk + tig + 4][m0 + g];                     \
                af[mt][3] = As[buf][kk + tig + 4][m0 + g + 8];                 \
            }                                                                  \
            _Pragma("unroll")                                                  \
            for (int nt = 0; nt < 4; nt++) {                                   \
                int n0 = wn + nt * 8;                                          \
                bf[nt][0] = Bs[buf][kk + tig][n0 + g];                         \
                bf[nt][1] = Bs[buf][kk + tig + 4][n0 + g];                     \
            }                                                                  \
            _Pragma("unroll")                                                  \
            for (int mt = 0; mt < 4; mt++)                                     \
                _Pragma("unroll")                                              \
                for (int nt = 0; nt < 4; nt++) {                               \
                    asm volatile(                                              \
                        "mma.sync.aligned.m16n8k8.row.col.f32.tf32.tf32.f32 "  \
                        "{%0,%1,%2,%3}, {%4,%5,%6,%7}, {%8,%9}, {%0,%1,%2,%3};"\
                        : "+f"(acc[mt][nt][0]), "+f"(acc[mt][nt][1]),          \
                          "+f"(acc[mt][nt][2]), "+f"(acc[mt][nt][3])           \
                        : "r"(af[mt][0]), "r"(af[mt][1]),                      \
                          "r"(af[mt][2]), "r"(af[mt][3]),                      \
                          "r"(bf[nt][0]), "r"(bf[nt][1]));                     \
                }                                                              \
        }                                                                      \
    } while (0)

    STORE_TILE(0);
    __syncthreads();

    int cur = 0;
    for (int k0 = 16; k0 < K; k0 += 16) {
        pa0 = *(const float4*)(Aptr + k0);
        pa1 = *(const float4*)(Aptr2 + k0);
        pb0 = *(const float4*)(Bptr + (size_t)k0 * N);
        pb1 = *(const float4*)(Bptr + (size_t)k0 * N + 64);

        COMPUTE_TILE(cur);
        STORE_TILE(cur ^ 1);
        __syncthreads();
        cur ^= 1;
    }
    COMPUTE_TILE(cur);

#pragma unroll
    for (int mt = 0; mt < 4; mt++) {
#pragma unroll
        for (int nt = 0; nt < 4; nt++) {
            int row = bm + wm + mt * 16 + g;
            int col = bn + wn + nt * 8 + tig * 2;
            *(float2*)&C[(size_t)row * N + col] =
                make_float2(acc[mt][nt][0], acc[mt][nt][1]);
            *(float2*)&C[(size_t)(row + 8) * N + col] =
                make_float2(acc[mt][nt][2], acc[mt][nt][3]);
        }
    }
#undef STORE_TILE
#undef COMPUTE_TILE
}

// ---------------------------------------------------------------------------
// Gather attention with online softmax + smem tiling of dense k/v rows.
// Block = 8 warps = 8 consecutive t, same h. Dense offsets (0..40) read rows
// [t0-40, t0+7] -> 48 rows staged in smem, reused by all 8 warps.
// Sparse offsets (128,384,1536) read L2 directly.
// ---------------------------------------------------------------------------
__global__ __launch_bounds__(256)
void attn_kernel(const float* __restrict__ pos_bias,    // [J, H]
                 const float* __restrict__ scale_embed, // [J, HD]
                 const float* __restrict__ if_gain)     // [H]
{
    __shared__ float s_k[48 * 64];
    __shared__ float s_v[48 * 64];
    __shared__ float s_se[J_DIM * HD_DIM];
    __shared__ float s_pb[J_DIM];

    const int tid  = threadIdx.x;
    const int w0   = blockIdx.x * 8;
    const int t0   = w0 & (T_DIM - 1);
    const int h    = w0 >> 11;
    const int lane = tid & 31;

    // Stage dense k/v rows [t0-40, t0+8) (clamped; masked scores make clamp safe)
    for (int i = tid; i < 48 * 64 / 4; i += 256) {
        int r = i >> 4;            // row 0..47 (16 float4 per row)
        int d = (i & 15) * 4;
        int gr = t0 - 40 + r;
        if (gr < 0) gr = 0;
        const float* kp = g_qkv + (size_t)gr * QKV_N + C_DIM + h * HD_DIM + d;
        *(float4*)&s_k[i * 4] = *(const float4*)kp;
        *(float4*)&s_v[i * 4] = *(const float4*)(kp + C_DIM);
    }
    for (int i = tid; i < J_DIM * HD_DIM; i += 256)
        s_se[i] = 1.0f + scale_embed[i];
    if (tid < J_DIM)
        s_pb[tid] = pos_bias[tid * H_DIM + h];
    __syncthreads();

    const int t = t0 + (tid >> 5);
    const float* base = g_qkv + (size_t)t * QKV_N + h * HD_DIM;
    float2 q = *(const float2*)(base + 2 * lane);

    const float scale = 0.125f;
    float m = -1e30f, l = 0.0f;
    float accx = 0.0f, accy = 0.0f;

#pragma unroll 4
    for (int j = 0; j < J_DIM; j++) {
        int dj   = c_deltas[j];
        int idx  = t - dj;
        float2 kk, vv;
        if (j < 41) {
            // dense: row r = (t - t0) + 40 - j  in [0,47]
            int r = (t - t0) + 40 - j;
            kk = *(const float2*)&s_k[r * 64 + 2 * lane];
            vv = *(const float2*)&s_v[r * 64 + 2 * lane];
        } else {
            int idxc = idx < 0 ? 0 : idx;
            const float* kp = g_qkv + (size_t)idxc * QKV_N + C_DIM + h * HD_DIM + 2 * lane;
            kk = *(const float2*)kp;
            vv = *(const float2*)(kp + C_DIM);
        }
        float2 se = *(const float2*)&s_se[j * HD_DIM + 2 * lane];

        float p = q.x * kk.x * se.x + q.y * kk.y * se.y;
        p += __shfl_xor_sync(0xffffffffu, p, 16);
        p += __shfl_xor_sync(0xffffffffu, p, 8);
        p += __shfl_xor_sync(0xffffffffu, p, 4);
        p += __shfl_xor_sync(0xffffffffu, p, 2);
        p += __shfl_xor_sync(0xffffffffu, p, 1);

        float s = (idx >= 0) ? fmaf(p, scale, s_pb[j]) : -1e30f;
        float mn = fmaxf(m, s);
        float corr = __expf(m - mn);
        float e = __expf(s - mn);
        l = l * corr + e;
        accx = accx * corr + e * vv.x;
        accy = accy * corr + e * vv.y;
        m = mn;
    }

    float gn = if_gain[h] / l;
    *(float2*)&g_attn[(size_t)t * C_DIM + h * HD_DIM + 2 * lane] =
        make_float2(accx * gn, accy * gn);
}

// ---------------------------------------------------------------------------
// Launch
// ---------------------------------------------------------------------------
extern "C" void kernel_launch(void* const* d_in, const int* in_sizes, int n_in,
                              void* d_out, int out_size)
{
    const float* x           = (const float*)d_in[0];
    const float* w_qkv       = (const float*)d_in[1];
    const float* w_out       = (const float*)d_in[2];
    const float* pos_bias    = (const float*)d_in[3];
    const float* scale_embed = (const float*)d_in[4];
    const float* if_gain     = (const float*)d_in[5];
    float* out = (float*)d_out;

    float* qkv_ptr = nullptr;
    float* attn_ptr = nullptr;
    cudaGetSymbolAddress((void**)&qkv_ptr, g_qkv);
    cudaGetSymbolAddress((void**)&attn_ptr, g_attn);

    // GEMM1: qkv = x @ w_qkv   [2048,1024]@[1024,3072]
    {
        dim3 grid(QKV_N / 128, T_DIM / 128);
        tf32_gemm<<<grid, 256>>>(x, w_qkv, qkv_ptr, T_DIM, QKV_N, C_DIM);
    }

    // Attention
    {
        int nwarps = T_DIM * H_DIM;
        attn_kernel<<<nwarps / 8, 256>>>(pos_bias, scale_embed, if_gain);
    }

    // GEMM2: out = attn @ w_out   [2048,1024]@[1024,1024]
    {
        dim3 grid(C_DIM / 128, T_DIM / 128);
        tf32_gemm<<<grid, 256>>>(attn_ptr, w_out, out, T_DIM, C_DIM, C_DIM);
    }
}

// round 5
// speedup vs baseline: 2.5968x; 1.0790x over previous
#include <cuda_runtime.h>
#include <cuda_bf16.h>
#include <cstdint>

// ---------------------------------------------------------------------------
// DSQGAttention, mma.sync.tf32 path (tcgen05 unavailable: PTX target sm_100).
// qkv = x @ w_qkv ; gather-attn (44 offsets) ; out = attn @ w_out
// T=2048, C=1024, H=16, HD=64, J=44, QKV_N=3072, K=1024 in both GEMMs.
// Inputs pre-rounded to tf32 so the GEMM mainloop is pure cp.async + ldmatrix
// + mma (no cvt/STS in the hot loop).
// ---------------------------------------------------------------------------

#define T_DIM 2048
#define C_DIM 1024
#define H_DIM 16
#define J_DIM 44
#define QKV_N 3072
#define K_DIM 1024

__device__ float g_qkv[T_DIM * QKV_N];    // fp32 qkv (already tf32-clean enough? q/k/v used in fp32 math; fine)
__device__ float g_attn[T_DIM * C_DIM];   // attention out, tf32-rounded
__device__ float g_xr[T_DIM * C_DIM];     // x, tf32-rounded
__device__ float g_wqt[QKV_N * K_DIM];    // w_qkv^T, tf32-rounded  [n][k]
__device__ float g_wot[C_DIM * K_DIM];    // w_out^T, tf32-rounded  [n][k]

__constant__ int c_deltas[J_DIM] = {
    0,1,2,3,4,5,6,7,8,9,10,11,12,13,14,15,16,17,18,19,
    20,21,22,23,24,25,26,27,28,29,30,31,32,33,34,35,36,37,38,39,
    40,128,384,1536
};

__device__ __forceinline__ uint32_t smem_u32(const void* p) {
    uint32_t a;
    asm("{ .reg .u64 t; cvta.to.shared.u64 t, %1; cvt.u32.u64 %0, t; }"
        : "=r"(a) : "l"(p));
    return a;
}
__device__ __forceinline__ float round_tf32(float f) {
    unsigned u;
    asm("cvt.rna.tf32.f32 %0, %1;" : "=r"(u) : "f"(f));
    return __uint_as_float(u);
}
__device__ __forceinline__ void cp16(uint32_t s, const void* g) {
    asm volatile("cp.async.cg.shared.global [%0], [%1], 16;" :: "r"(s), "l"(g));
}
#define CP_COMMIT() asm volatile("cp.async.commit_group;" ::: "memory")
#define CP_WAIT2()  asm volatile("cp.async.wait_group 2;" ::: "memory")

__device__ __forceinline__ void ldsm_x4(uint32_t& r0, uint32_t& r1,
                                        uint32_t& r2, uint32_t& r3, uint32_t a) {
    asm volatile("ldmatrix.sync.aligned.m8n8.x4.shared.b16 {%0,%1,%2,%3}, [%4];"
                 : "=r"(r0), "=r"(r1), "=r"(r2), "=r"(r3) : "r"(a));
}

// ---------------------------------------------------------------------------
// Pre-pass: tf32-round in place layout (x -> g_xr)
// ---------------------------------------------------------------------------
__global__ void round_kernel(const float* __restrict__ src, float* __restrict__ dst, int n4)
{
    int i = blockIdx.x * blockDim.x + threadIdx.x;
    if (i >= n4) return;
    float4 v = ((const float4*)src)[i];
    ((float4*)dst)[i] = make_float4(round_tf32(v.x), round_tf32(v.y),
                                    round_tf32(v.z), round_tf32(v.w));
}

// ---------------------------------------------------------------------------
// Pre-pass: transpose [R][Cc] -> [Cc][R] with tf32 rounding
// ---------------------------------------------------------------------------
__global__ void tround_kernel(const float* __restrict__ src, float* __restrict__ dst,
                              int R, int Cc)
{
    __shared__ float tile[32][33];
    int bx = blockIdx.x, by = blockIdx.y;
    int tx = threadIdx.x, ty = threadIdx.y;
#pragma unroll
    for (int i = 0; i < 4; i++)
        tile[ty + 8*i][tx] = src[(size_t)(by*32 + ty + 8*i) * Cc + bx*32 + tx];
    __syncthreads();
#pragma unroll
    for (int i = 0; i < 4; i++)
        dst[(size_t)(bx*32 + ty + 8*i) * R + by*32 + tx] = round_tf32(tile[tx][ty + 8*i]);
}

// ---------------------------------------------------------------------------
// TF32 GEMM: C[M,N] = A[M,K] @ B[N,K]^T, A=[m][k], B=[n][k], K=1024.
// Block 128x128, BK=32, 4-stage cp.async pipeline, ldmatrix fragments.
// 8 warps (2m x 4n), warp tile 64x32.
// smem per stage: A 128*128B + B 128*128B = 32KB; 4 stages = 128KB dynamic.
// ---------------------------------------------------------------------------
#define GEMM_SMEM (4 * 32768)
#define N_CHUNK (K_DIM / 32)   // 32

__global__ __launch_bounds__(256, 1)
void tf32_gemm(const float* __restrict__ A, const float* __restrict__ B,
               float* __restrict__ C, int M, int N)
{
    extern __shared__ __align__(1024) char dyn_smem[];
    const uint32_t dsm = smem_u32(dyn_smem);

    const int tid  = threadIdx.x;
    const int wid  = tid >> 5;
    const int lane = tid & 31;
    const int bm = blockIdx.y * 128;
    const int bn = blockIdx.x * 128;
    const int wm = (wid & 1) * 64;
    const int wn = (wid >> 1) * 32;
    const int g   = lane >> 2;
    const int tig = lane & 3;

    // cp.async geometry: 4 consecutive 16B segs per thread per matrix
    const int ld_row = tid >> 1;            // 0..127
    const int ld_s0  = (tid & 1) * 4;       // seg 0..7 base
    const float* gA = A + (size_t)(bm + ld_row) * K_DIM + ld_s0 * 4;
    const float* gB = B + (size_t)(bn + ld_row) * K_DIM + ld_s0 * 4;
    const int ld_swz = (ld_row & 7) << 4;
    const uint32_t sA_row = ld_row * 128;

    // ldmatrix geometry
    const int swz   = (lane & 7) << 4;
    const int a_row = wm + (((lane >> 3) & 1) << 3) + (lane & 7);
    const int a_s16 = (lane >> 4) << 4;
    const int b_s16 = ((lane >> 3) & 1) << 4;
    const int b_rw  = wn + ((lane >> 4) << 3) + (lane & 7);

    float acc[4][4][4];
#pragma unroll
    for (int mt = 0; mt < 4; mt++)
#pragma unroll
        for (int nt = 0; nt < 4; nt++)
#pragma unroll
            for (int r = 0; r < 4; r++) acc[mt][nt][r] = 0.0f;

#define ISSUE_CHUNK(c, buf)                                                    \
    do {                                                                       \
        const uint32_t sb = dsm + (buf) * 32768;                               \
        const int kf = (c) * 32;                                               \
        _Pragma("unroll")                                                      \
        for (int i = 0; i < 4; i++) {                                          \
            const int sg = ld_s0 + i;                                          \
            const uint32_t so = sA_row + ((sg * 16) ^ ld_swz);                 \
            cp16(sb + so,         gA + kf + i * 4);                            \
            cp16(sb + 16384 + so, gB + kf + i * 4);                            \
        }                                                                      \
    } while (0)

    ISSUE_CHUNK(0, 0); CP_COMMIT();
    ISSUE_CHUNK(1, 1); CP_COMMIT();
    ISSUE_CHUNK(2, 2); CP_COMMIT();

    for (int c = 0; c < N_CHUNK; c++) {
        CP_WAIT2();
        __syncthreads();

        const uint32_t aB = dsm + (c & 3) * 32768;
        const uint32_t bB = aB + 16384;
        const uint32_t a_base = aB + a_row * 128;
        const uint32_t b_base = bB + b_rw * 128;

#pragma unroll
        for (int kk = 0; kk < 4; kk++) {
            uint32_t af[4][4], bf[4][2];
            const uint32_t kbA = (uint32_t)((kk * 32 + a_s16) ^ swz);
            const uint32_t kbB = (uint32_t)((kk * 32 + b_s16) ^ swz);
#pragma unroll
            for (int mt = 0; mt < 4; mt++)
                ldsm_x4(af[mt][0], af[mt][1], af[mt][2], af[mt][3],
                        a_base + mt * 2048 + kbA);
#pragma unroll
            for (int p = 0; p < 2; p++)
                ldsm_x4(bf[2*p][0], bf[2*p][1], bf[2*p+1][0], bf[2*p+1][1],
                        b_base + p * 2048 + kbB);
#pragma unroll
            for (int mt = 0; mt < 4; mt++)
#pragma unroll
                for (int nt = 0; nt < 4; nt++) {
                    asm volatile(
                        "mma.sync.aligned.m16n8k8.row.col.f32.tf32.tf32.f32 "
                        "{%0,%1,%2,%3}, {%4,%5,%6,%7}, {%8,%9}, {%0,%1,%2,%3};"
                        : "+f"(acc[mt][nt][0]), "+f"(acc[mt][nt][1]),
                          "+f"(acc[mt][nt][2]), "+f"(acc[mt][nt][3])
                        : "r"(af[mt][0]), "r"(af[mt][1]),
                          "r"(af[mt][2]), "r"(af[mt][3]),
                          "r"(bf[nt][0]), "r"(bf[nt][1]));
                }
        }

        if (c + 3 < N_CHUNK) ISSUE_CHUNK(c + 3, (c + 3) & 3);
        CP_COMMIT();
    }
#undef ISSUE_CHUNK

#pragma unroll
    for (int mt = 0; mt < 4; mt++) {
#pragma unroll
        for (int nt = 0; nt < 4; nt++) {
            int row = bm + wm + mt * 16 + g;
            int col = bn + wn + nt * 8 + tig * 2;
            *(float2*)&C[(size_t)row * N + col] =
                make_float2(acc[mt][nt][0], acc[mt][nt][1]);
            *(float2*)&C[(size_t)(row + 8) * N + col] =
                make_float2(acc[mt][nt][2], acc[mt][nt][3]);
        }
    }
}

// ---------------------------------------------------------------------------
// Gather attention: float4-per-lane, batched softmax, tf32-rounded output.
// Block = 256 thr = 8 warps = 8 consecutive t, one h. Warp = 2 halves of
// 16 lanes; half handles j = 2*jj + half per pass (22 passes).
// ---------------------------------------------------------------------------
__global__ __launch_bounds__(256)
void attn_kernel(const float* __restrict__ pos_bias,    // [J, H]
                 const float* __restrict__ scale_embed, // [J, 64]
                 const float* __restrict__ if_gain)     // [H]
{
    __shared__ float s_k[48 * 64];
    __shared__ float s_v[48 * 64];
    __shared__ float s_se[J_DIM * 64];
    __shared__ float s_pb[J_DIM];

    const int tid  = threadIdx.x;
    const int lane = tid & 31;
    const int warp = tid >> 5;
    const int w0   = blockIdx.x * 8;
    const int t0   = w0 & (T_DIM - 1);
    const int h    = w0 >> 11;
    const int half = lane >> 4;
    const int sl   = lane & 15;

    for (int i = tid; i < 48 * 16; i += 256) {
        int r = i >> 4, d = (i & 15) * 4;
        int gr = t0 - 40 + r;
        if (gr < 0) gr = 0;
        const float* kp = g_qkv + (size_t)gr * QKV_N + C_DIM + h * 64 + d;
        *(float4*)&s_k[r * 64 + d] = *(const float4*)kp;
        *(float4*)&s_v[r * 64 + d] = *(const float4*)(kp + C_DIM);
    }
    for (int i = tid; i < J_DIM * 16; i += 256) {
        float4 v = ((const float4*)scale_embed)[i];
        ((float4*)s_se)[i] = make_float4(1.f + v.x, 1.f + v.y, 1.f + v.z, 1.f + v.w);
    }
    if (tid < J_DIM) s_pb[tid] = pos_bias[tid * H_DIM + h];
    __syncthreads();

    const int t = t0 + warp;
    const float4 q = *(const float4*)(g_qkv + (size_t)t * QKV_N + h * 64 + sl * 4);

    float sc0 = -1e30f, sc1 = -1e30f;
#pragma unroll
    for (int jj = 0; jj < 22; jj++) {
        const int j = 2 * jj + half;
        const int idx = t - c_deltas[j];
        float4 kk;
        if (j < 41) {
            int r = t - t0 + 40 - j;
            kk = *(const float4*)&s_k[r * 64 + sl * 4];
        } else {
            int ic = idx < 0 ? 0 : idx;
            kk = *(const float4*)(g_qkv + (size_t)ic * QKV_N + C_DIM + h * 64 + sl * 4);
        }
        const float4 se = *(const float4*)&s_se[j * 64 + sl * 4];
        float p = q.x * kk.x * se.x + q.y * kk.y * se.y
                + q.z * kk.z * se.z + q.w * kk.w * se.w;
        p += __shfl_xor_sync(0xffffffffu, p, 8);
        p += __shfl_xor_sync(0xffffffffu, p, 4);
        p += __shfl_xor_sync(0xffffffffu, p, 2);
        p += __shfl_xor_sync(0xffffffffu, p, 1);
        float sv = (idx >= 0) ? fmaf(p, 0.125f, s_pb[j]) : -1e30f;
        if (jj < 16) { if (sl == jj) sc0 = sv; }
        else         { if (sl == jj - 16) sc1 = sv; }
    }

    float mm = fmaxf(sc0, sc1);
#pragma unroll
    for (int o = 16; o; o >>= 1) mm = fmaxf(mm, __shfl_xor_sync(0xffffffffu, mm, o));
    const float e0 = __expf(sc0 - mm);
    const float e1 = (sl < 6) ? __expf(sc1 - mm) : 0.0f;
    float ls = e0 + e1;
#pragma unroll
    for (int o = 16; o; o >>= 1) ls += __shfl_xor_sync(0xffffffffu, ls, o);

    float4 acc = make_float4(0.f, 0.f, 0.f, 0.f);
#pragma unroll
    for (int jj = 0; jj < 22; jj++) {
        const int j = 2 * jj + half;
        const float val = (jj < 16) ? e0 : e1;
        const float ej = __shfl_sync(0xffffffffu, val, (jj & 15) + (half << 4));
        float4 vv;
        if (j < 41) {
            int r = t - t0 + 40 - j;
            vv = *(const float4*)&s_v[r * 64 + sl * 4];
        } else {
            int ic = t - c_deltas[j];
            if (ic < 0) ic = 0;
            vv = *(const float4*)(g_qkv + (size_t)ic * QKV_N + 2 * C_DIM + h * 64 + sl * 4);
        }
        acc.x = fmaf(ej, vv.x, acc.x);
        acc.y = fmaf(ej, vv.y, acc.y);
        acc.z = fmaf(ej, vv.z, acc.z);
        acc.w = fmaf(ej, vv.w, acc.w);
    }
    acc.x += __shfl_xor_sync(0xffffffffu, acc.x, 16);
    acc.y += __shfl_xor_sync(0xffffffffu, acc.y, 16);
    acc.z += __shfl_xor_sync(0xffffffffu, acc.z, 16);
    acc.w += __shfl_xor_sync(0xffffffffu, acc.w, 16);

    if (half == 0) {
        const float gn = if_gain[h] / ls;
        *(float4*)&g_attn[(size_t)t * C_DIM + h * 64 + sl * 4] = make_float4(
            round_tf32(acc.x * gn), round_tf32(acc.y * gn),
            round_tf32(acc.z * gn), round_tf32(acc.w * gn));
    }
}

// ---------------------------------------------------------------------------
// Launch
// ---------------------------------------------------------------------------
extern "C" void kernel_launch(void* const* d_in, const int* in_sizes, int n_in,
                              void* d_out, int out_size)
{
    const float* x           = (const float*)d_in[0];
    const float* w_qkv       = (const float*)d_in[1];
    const float* w_out       = (const float*)d_in[2];
    const float* pos_bias    = (const float*)d_in[3];
    const float* scale_embed = (const float*)d_in[4];
    const float* if_gain     = (const float*)d_in[5];
    float* out = (float*)d_out;

    float *qkv_p, *attn_p, *xr, *wqt, *wot;
    cudaGetSymbolAddress((void**)&qkv_p, g_qkv);
    cudaGetSymbolAddress((void**)&attn_p, g_attn);
    cudaGetSymbolAddress((void**)&xr, g_xr);
    cudaGetSymbolAddress((void**)&wqt, g_wqt);
    cudaGetSymbolAddress((void**)&wot, g_wot);

    static bool attr_set = false;
    if (!attr_set) {
        cudaFuncSetAttribute(tf32_gemm, cudaFuncAttributeMaxDynamicSharedMemorySize,
                             GEMM_SMEM);
        attr_set = true;
    }

    // Pre-pass: round x; transpose+round weights
    round_kernel<<<(T_DIM * C_DIM / 4 + 255) / 256, 256>>>(x, xr, T_DIM * C_DIM / 4);
    tround_kernel<<<dim3(QKV_N / 32, C_DIM / 32), dim3(32, 8)>>>(w_qkv, wqt, C_DIM, QKV_N);
    tround_kernel<<<dim3(C_DIM / 32, C_DIM / 32), dim3(32, 8)>>>(w_out, wot, C_DIM, C_DIM);

    // GEMM1: qkv = x @ w_qkv
    tf32_gemm<<<dim3(QKV_N / 128, T_DIM / 128), 256, GEMM_SMEM>>>(
        xr, wqt, qkv_p, T_DIM, QKV_N);

    // Attention
    attn_kernel<<<T_DIM * H_DIM / 8, 256>>>(pos_bias, scale_embed, if_gain);

    // GEMM2: out = attn @ w_out
    tf32_gemm<<<dim3(C_DIM / 128, T_DIM / 128), 256, GEMM_SMEM>>>(
        attn_p, wot, out, T_DIM, C_DIM);
}

// round 6
// speedup vs baseline: 2.7925x; 1.0753x over previous
#include <cuda_runtime.h>
#include <cuda_bf16.h>
#include <cstdint>

// ---------------------------------------------------------------------------
// DSQGAttention, mma.sync.tf32 path (tcgen05 unavailable: PTX target sm_100).
// qkv = x @ w_qkv ; gather-attn (44 offsets) ; out = attn @ w_out
// T=2048, C=1024, H=16, HD=64, J=44, QKV_N=3072, K=1024 in both GEMMs.
// Inputs pre-rounded to tf32; GEMM mainloop = cp.async + ldmatrix + mma.
// R6: 3-stage pipeline (96KB) + __launch_bounds__(256,2) -> 2 CTA/SM.
// ---------------------------------------------------------------------------

#define T_DIM 2048
#define C_DIM 1024
#define H_DIM 16
#define J_DIM 44
#define QKV_N 3072
#define K_DIM 1024

__device__ float g_qkv[T_DIM * QKV_N];    // fp32 qkv
__device__ float g_attn[T_DIM * C_DIM];   // attention out, tf32-rounded
__device__ float g_xr[T_DIM * C_DIM];     // x, tf32-rounded
__device__ float g_wqt[QKV_N * K_DIM];    // w_qkv^T, tf32-rounded  [n][k]
__device__ float g_wot[C_DIM * K_DIM];    // w_out^T, tf32-rounded  [n][k]

__constant__ int c_deltas[J_DIM] = {
    0,1,2,3,4,5,6,7,8,9,10,11,12,13,14,15,16,17,18,19,
    20,21,22,23,24,25,26,27,28,29,30,31,32,33,34,35,36,37,38,39,
    40,128,384,1536
};

__device__ __forceinline__ uint32_t smem_u32(const void* p) {
    uint32_t a;
    asm("{ .reg .u64 t; cvta.to.shared.u64 t, %1; cvt.u32.u64 %0, t; }"
        : "=r"(a) : "l"(p));
    return a;
}
__device__ __forceinline__ float round_tf32(float f) {
    unsigned u;
    asm("cvt.rna.tf32.f32 %0, %1;" : "=r"(u) : "f"(f));
    return __uint_as_float(u);
}
__device__ __forceinline__ void cp16(uint32_t s, const void* g) {
    asm volatile("cp.async.cg.shared.global [%0], [%1], 16;" :: "r"(s), "l"(g));
}
#define CP_COMMIT() asm volatile("cp.async.commit_group;" ::: "memory")
#define CP_WAIT1()  asm volatile("cp.async.wait_group 1;" ::: "memory")

__device__ __forceinline__ void ldsm_x4(uint32_t& r0, uint32_t& r1,
                                        uint32_t& r2, uint32_t& r3, uint32_t a) {
    asm volatile("ldmatrix.sync.aligned.m8n8.x4.shared.b16 {%0,%1,%2,%3}, [%4];"
                 : "=r"(r0), "=r"(r1), "=r"(r2), "=r"(r3) : "r"(a));
}

// ---------------------------------------------------------------------------
// Pre-pass: tf32-round (same layout)
// ---------------------------------------------------------------------------
__global__ void round_kernel(const float* __restrict__ src, float* __restrict__ dst, int n4)
{
    int i = blockIdx.x * blockDim.x + threadIdx.x;
    if (i >= n4) return;
    float4 v = ((const float4*)src)[i];
    ((float4*)dst)[i] = make_float4(round_tf32(v.x), round_tf32(v.y),
                                    round_tf32(v.z), round_tf32(v.w));
}

// ---------------------------------------------------------------------------
// Pre-pass: transpose [R][Cc] -> [Cc][R] with tf32 rounding
// ---------------------------------------------------------------------------
__global__ void tround_kernel(const float* __restrict__ src, float* __restrict__ dst,
                              int R, int Cc)
{
    __shared__ float tile[32][33];
    int bx = blockIdx.x, by = blockIdx.y;
    int tx = threadIdx.x, ty = threadIdx.y;
#pragma unroll
    for (int i = 0; i < 4; i++)
        tile[ty + 8*i][tx] = src[(size_t)(by*32 + ty + 8*i) * Cc + bx*32 + tx];
    __syncthreads();
#pragma unroll
    for (int i = 0; i < 4; i++)
        dst[(size_t)(bx*32 + ty + 8*i) * R + by*32 + tx] = round_tf32(tile[tx][ty + 8*i]);
}

// ---------------------------------------------------------------------------
// TF32 GEMM: C[M,N] = A[M,K] @ B[N,K]^T, A=[m][k], B=[n][k], K=1024.
// Block 128x128, BK=32, 3-stage cp.async pipeline, ldmatrix fragments.
// 8 warps (2m x 4n), warp tile 64x32. 96KB smem -> 2 CTA/SM.
// ---------------------------------------------------------------------------
#define GEMM_SMEM (3 * 32768)
#define N_CHUNK (K_DIM / 32)   // 32

__global__ __launch_bounds__(256, 2)
void tf32_gemm(const float* __restrict__ A, const float* __restrict__ B,
               float* __restrict__ C, int M, int N)
{
    extern __shared__ __align__(1024) char dyn_smem[];
    const uint32_t dsm = smem_u32(dyn_smem);

    const int tid  = threadIdx.x;
    const int wid  = tid >> 5;
    const int lane = tid & 31;
    const int bm = blockIdx.y * 128;
    const int bn = blockIdx.x * 128;
    const int wm = (wid & 1) * 64;
    const int wn = (wid >> 1) * 32;
    const int g   = lane >> 2;
    const int tig = lane & 3;

    // cp.async geometry: 4 consecutive 16B segs per thread per matrix
    const int ld_row = tid >> 1;            // 0..127
    const int ld_s0  = (tid & 1) * 4;       // seg base
    const float* gA = A + (size_t)(bm + ld_row) * K_DIM + ld_s0 * 4;
    const float* gB = B + (size_t)(bn + ld_row) * K_DIM + ld_s0 * 4;
    const int ld_swz = (ld_row & 7) << 4;
    const uint32_t sA_row = ld_row * 128;

    // ldmatrix geometry
    const int swz   = (lane & 7) << 4;
    const int a_row = wm + (((lane >> 3) & 1) << 3) + (lane & 7);
    const int a_s16 = (lane >> 4) << 4;
    const int b_s16 = ((lane >> 3) & 1) << 4;
    const int b_rw  = wn + ((lane >> 4) << 3) + (lane & 7);

    float acc[4][4][4];
#pragma unroll
    for (int mt = 0; mt < 4; mt++)
#pragma unroll
        for (int nt = 0; nt < 4; nt++)
#pragma unroll
            for (int r = 0; r < 4; r++) acc[mt][nt][r] = 0.0f;

#define ISSUE_CHUNK(c, buf)                                                    \
    do {                                                                       \
        const uint32_t sb = dsm + (buf) * 32768;                               \
        const int kf = (c) * 32;                                               \
        _Pragma("unroll")                                                      \
        for (int i = 0; i < 4; i++) {                                          \
            const int sg = ld_s0 + i;                                          \
            const uint32_t so = sA_row + ((sg * 16) ^ ld_swz);                 \
            cp16(sb + so,         gA + kf + i * 4);                            \
            cp16(sb + 16384 + so, gB + kf + i * 4);                            \
        }                                                                      \
    } while (0)

    ISSUE_CHUNK(0, 0); CP_COMMIT();
    ISSUE_CHUNK(1, 1); CP_COMMIT();

    for (int c = 0; c < N_CHUNK; c++) {
        CP_WAIT1();
        __syncthreads();

        const int buf = c % 3;
        const uint32_t aB = dsm + buf * 32768;
        const uint32_t bB = aB + 16384;
        const uint32_t a_base = aB + a_row * 128;
        const uint32_t b_base = bB + b_rw * 128;

#pragma unroll
        for (int kk = 0; kk < 4; kk++) {
            uint32_t af[4][4], bf[4][2];
            const uint32_t kbA = (uint32_t)((kk * 32 + a_s16) ^ swz);
            const uint32_t kbB = (uint32_t)((kk * 32 + b_s16) ^ swz);
#pragma unroll
            for (int mt = 0; mt < 4; mt++)
                ldsm_x4(af[mt][0], af[mt][1], af[mt][2], af[mt][3],
                        a_base + mt * 2048 + kbA);
#pragma unroll
            for (int p = 0; p < 2; p++)
                ldsm_x4(bf[2*p][0], bf[2*p][1], bf[2*p+1][0], bf[2*p+1][1],
                        b_base + p * 2048 + kbB);
#pragma unroll
            for (int mt = 0; mt < 4; mt++)
#pragma unroll
                for (int nt = 0; nt < 4; nt++) {
                    asm volatile(
                        "mma.sync.aligned.m16n8k8.row.col.f32.tf32.tf32.f32 "
                        "{%0,%1,%2,%3}, {%4,%5,%6,%7}, {%8,%9}, {%0,%1,%2,%3};"
                        : "+f"(acc[mt][nt][0]), "+f"(acc[mt][nt][1]),
                          "+f"(acc[mt][nt][2]), "+f"(acc[mt][nt][3])
                        : "r"(af[mt][0]), "r"(af[mt][1]),
                          "r"(af[mt][2]), "r"(af[mt][3]),
                          "r"(bf[nt][0]), "r"(bf[nt][1]));
                }
        }

        if (c + 2 < N_CHUNK) ISSUE_CHUNK(c + 2, (c + 2) % 3);
        CP_COMMIT();
    }
#undef ISSUE_CHUNK

#pragma unroll
    for (int mt = 0; mt < 4; mt++) {
#pragma unroll
        for (int nt = 0; nt < 4; nt++) {
            int row = bm + wm + mt * 16 + g;
            int col = bn + wn + nt * 8 + tig * 2;
            *(float2*)&C[(size_t)row * N + col] =
                make_float2(acc[mt][nt][0], acc[mt][nt][1]);
            *(float2*)&C[(size_t)(row + 8) * N + col] =
                make_float2(acc[mt][nt][2], acc[mt][nt][3]);
        }
    }
}

// ---------------------------------------------------------------------------
// Gather attention: float4-per-lane, batched softmax, tf32-rounded output.
// Block = 256 thr = 8 warps = 8 consecutive t, one h.
// ---------------------------------------------------------------------------
__global__ __launch_bounds__(256)
void attn_kernel(const float* __restrict__ pos_bias,    // [J, H]
                 const float* __restrict__ scale_embed, // [J, 64]
                 const float* __restrict__ if_gain)     // [H]
{
    __shared__ float s_k[48 * 64];
    __shared__ float s_v[48 * 64];
    __shared__ float s_se[J_DIM * 64];
    __shared__ float s_pb[J_DIM];

    const int tid  = threadIdx.x;
    const int lane = tid & 31;
    const int warp = tid >> 5;
    const int w0   = blockIdx.x * 8;
    const int t0   = w0 & (T_DIM - 1);
    const int h    = w0 >> 11;
    const int half = lane >> 4;
    const int sl   = lane & 15;

    for (int i = tid; i < 48 * 16; i += 256) {
        int r = i >> 4, d = (i & 15) * 4;
        int gr = t0 - 40 + r;
        if (gr < 0) gr = 0;
        const float* kp = g_qkv + (size_t)gr * QKV_N + C_DIM + h * 64 + d;
        *(float4*)&s_k[r * 64 + d] = *(const float4*)kp;
        *(float4*)&s_v[r * 64 + d] = *(const float4*)(kp + C_DIM);
    }
    for (int i = tid; i < J_DIM * 16; i += 256) {
        float4 v = ((const float4*)scale_embed)[i];
        ((float4*)s_se)[i] = make_float4(1.f + v.x, 1.f + v.y, 1.f + v.z, 1.f + v.w);
    }
    if (tid < J_DIM) s_pb[tid] = pos_bias[tid * H_DIM + h];
    __syncthreads();

    const int t = t0 + warp;
    const float4 q = *(const float4*)(g_qkv + (size_t)t * QKV_N + h * 64 + sl * 4);

    float sc0 = -1e30f, sc1 = -1e30f;
#pragma unroll
    for (int jj = 0; jj < 22; jj++) {
        const int j = 2 * jj + half;
        const int idx = t - c_deltas[j];
        float4 kk;
        if (j < 41) {
            int r = t - t0 + 40 - j;
            kk = *(const float4*)&s_k[r * 64 + sl * 4];
        } else {
            int ic = idx < 0 ? 0 : idx;
            kk = *(const float4*)(g_qkv + (size_t)ic * QKV_N + C_DIM + h * 64 + sl * 4);
        }
        const float4 se = *(const float4*)&s_se[j * 64 + sl * 4];
        float p = q.x * kk.x * se.x + q.y * kk.y * se.y
                + q.z * kk.z * se.z + q.w * kk.w * se.w;
        p += __shfl_xor_sync(0xffffffffu, p, 8);
        p += __shfl_xor_sync(0xffffffffu, p, 4);
        p += __shfl_xor_sync(0xffffffffu, p, 2);
        p += __shfl_xor_sync(0xffffffffu, p, 1);
        float sv = (idx >= 0) ? fmaf(p, 0.125f, s_pb[j]) : -1e30f;
        if (jj < 16) { if (sl == jj) sc0 = sv; }
        else         { if (sl == jj - 16) sc1 = sv; }
    }

    float mm = fmaxf(sc0, sc1);
#pragma unroll
    for (int o = 16; o; o >>= 1) mm = fmaxf(mm, __shfl_xor_sync(0xffffffffu, mm, o));
    const float e0 = __expf(sc0 - mm);
    const float e1 = (sl < 6) ? __expf(sc1 - mm) : 0.0f;
    float ls = e0 + e1;
#pragma unroll
    for (int o = 16; o; o >>= 1) ls += __shfl_xor_sync(0xffffffffu, ls, o);

    float4 acc = make_float4(0.f, 0.f, 0.f, 0.f);
#pragma unroll
    for (int jj = 0; jj < 22; jj++) {
        const int j = 2 * jj + half;
        const float val = (jj < 16) ? e0 : e1;
        const float ej = __shfl_sync(0xffffffffu, val, (jj & 15) + (half << 4));
        float4 vv;
        if (j < 41) {
            int r = t - t0 + 40 - j;
            vv = *(const float4*)&s_v[r * 64 + sl * 4];
        } else {
            int ic = t - c_deltas[j];
            if (ic < 0) ic = 0;
            vv = *(const float4*)(g_qkv + (size_t)ic * QKV_N + 2 * C_DIM + h * 64 + sl * 4);
        }
        acc.x = fmaf(ej, vv.x, acc.x);
        acc.y = fmaf(ej, vv.y, acc.y);
        acc.z = fmaf(ej, vv.z, acc.z);
        acc.w = fmaf(ej, vv.w, acc.w);
    }
    acc.x += __shfl_xor_sync(0xffffffffu, acc.x, 16);
    acc.y += __shfl_xor_sync(0xffffffffu, acc.y, 16);
    acc.z += __shfl_xor_sync(0xffffffffu, acc.z, 16);
    acc.w += __shfl_xor_sync(0xffffffffu, acc.w, 16);

    if (half == 0) {
        const float gn = if_gain[h] / ls;
        *(float4*)&g_attn[(size_t)t * C_DIM + h * 64 + sl * 4] = make_float4(
            round_tf32(acc.x * gn), round_tf32(acc.y * gn),
            round_tf32(acc.z * gn), round_tf32(acc.w * gn));
    }
}

// ---------------------------------------------------------------------------
// Launch
// ---------------------------------------------------------------------------
extern "C" void kernel_launch(void* const* d_in, const int* in_sizes, int n_in,
                              void* d_out, int out_size)
{
    const float* x           = (const float*)d_in[0];
    const float* w_qkv       = (const float*)d_in[1];
    const float* w_out       = (const float*)d_in[2];
    const float* pos_bias    = (const float*)d_in[3];
    const float* scale_embed = (const float*)d_in[4];
    const float* if_gain     = (const float*)d_in[5];
    float* out = (float*)d_out;

    float *qkv_p, *attn_p, *xr, *wqt, *wot;
    cudaGetSymbolAddress((void**)&qkv_p, g_qkv);
    cudaGetSymbolAddress((void**)&attn_p, g_attn);
    cudaGetSymbolAddress((void**)&xr, g_xr);
    cudaGetSymbolAddress((void**)&wqt, g_wqt);
    cudaGetSymbolAddress((void**)&wot, g_wot);

    cudaFuncSetAttribute(tf32_gemm, cudaFuncAttributeMaxDynamicSharedMemorySize,
                         GEMM_SMEM);

    // Pre-pass: round x; transpose+round weights
    round_kernel<<<(T_DIM * C_DIM / 4 + 255) / 256, 256>>>(x, xr, T_DIM * C_DIM / 4);
    tround_kernel<<<dim3(QKV_N / 32, C_DIM / 32), dim3(32, 8)>>>(w_qkv, wqt, C_DIM, QKV_N);
    tround_kernel<<<dim3(C_DIM / 32, C_DIM / 32), dim3(32, 8)>>>(w_out, wot, C_DIM, C_DIM);

    // GEMM1: qkv = x @ w_qkv
    tf32_gemm<<<dim3(QKV_N / 128, T_DIM / 128), 256, GEMM_SMEM>>>(
        xr, wqt, qkv_p, T_DIM, QKV_N);

    // Attention
    attn_kernel<<<T_DIM * H_DIM / 8, 256>>>(pos_bias, scale_embed, if_gain);

    // GEMM2: out = attn @ w_out
    tf32_gemm<<<dim3(C_DIM / 128, T_DIM / 128), 256, GEMM_SMEM>>>(
        attn_p, wot, out, T_DIM, C_DIM);
}